// round 10
// baseline (speedup 1.0000x reference)
#include <cuda_runtime.h>
#include <cuda_fp16.h>
#include <math.h>

#define Hh 2048
#define Tt 4096
#define Dd 66
#define G4H (4*Hh)
#define NBLK 148
#define NTHR 512
#define NWARP (NTHR/32)
#define WELEM ((size_t)G4H*(size_t)Hh)
#define PROW 2056                        // pinned row stride in halves (bank-conflict-free)
#define PSLOT (16*PROW)
#define SWBYTES (3*PSLOT*sizeof(__half)) // 197376 B: 3 pinned 16-row tiles

// ---------------- persistent device state (static; no runtime allocs) -------
__device__ float  g_h1[2][Hh];
__device__ float  g_h2[2][Hh];
__device__ float  g_h2hist[Tt][Hh];                // 33.5 MB
__device__ __half g_pre1[(size_t)Tt * G4H];        // 67 MB fp16 (streamed, .cs)
__device__ __half g_whh1[WELEM];                   // 33.5 MB fp16
__device__ __half g_wih2[WELEM];
__device__ __half g_whh2[WELEM];

// flag barrier state (monotonic across graph replays)
__device__ volatile unsigned g_arrive[NBLK];
__device__ volatile unsigned g_release;

__device__ __forceinline__ float sigf(float x) { return 1.0f / (1.0f + expf(-x)); }

// ---------------- flag-based grid barrier -----------------------------------
__device__ __forceinline__ void gbar(unsigned target) {
    __syncthreads();
    if (blockIdx.x == 0) {
        if (threadIdx.x > 0 && threadIdx.x < NBLK) {
            while ((int)(g_arrive[threadIdx.x] - target) < 0) { }
        }
        __syncthreads();
        if (threadIdx.x == 0) { __threadfence(); g_release = target; }
    } else {
        if (threadIdx.x == 0) {
            __threadfence();
            g_arrive[blockIdx.x] = target;
            while ((int)(g_release - target) < 0) { }
            __threadfence();
        }
    }
    __syncthreads();
}

// ---------------- helpers ----------------------------------------------------
__device__ __forceinline__ float wreduce(float s) {
#pragma unroll
    for (int o = 16; o; o >>= 1) s += __shfl_down_sync(0xffffffffu, s, o);
    return s;
}

// One MMA task: 16 gate rows x K=2048 dot against fp16 vector hv.
// A = weight rows (row-major, stride `rs` halves between the two row groups'
// pointers baked in by caller), B = hv in column 0 (other cols zero).
// Returns D[g][0] in c0 and D[g+8][0] in c2 for lanes with tig==0.
__device__ __forceinline__ void mma_dot(const __half* __restrict__ rp_lo,
                                        const __half* __restrict__ rp_hi,
                                        const __half* __restrict__ hv,
                                        int g, int tig,
                                        float& c0, float& c2) {
    float d0 = 0.f, d1 = 0.f, d2 = 0.f, d3 = 0.f;
    const __half* plo = rp_lo + 2 * tig;
    const __half* phi = rp_hi + 2 * tig;
    const __half* pb  = hv + 2 * tig;
#pragma unroll 8
    for (int k0 = 0; k0 < Hh; k0 += 16) {
        unsigned a0 = *(const unsigned*)(plo + k0);
        unsigned a2 = *(const unsigned*)(plo + k0 + 8);
        unsigned a1 = *(const unsigned*)(phi + k0);
        unsigned a3 = *(const unsigned*)(phi + k0 + 8);
        unsigned bv0 = *(const unsigned*)(pb + k0);
        unsigned bv1 = *(const unsigned*)(pb + k0 + 8);
        unsigned b0 = (g == 0) ? bv0 : 0u;
        unsigned b1 = (g == 0) ? bv1 : 0u;
        asm("mma.sync.aligned.m16n8k16.row.col.f32.f16.f16.f32 "
            "{%0,%1,%2,%3}, {%4,%5,%6,%7}, {%8,%9}, {%0,%1,%2,%3};"
            : "+f"(d0), "+f"(d1), "+f"(d2), "+f"(d3)
            : "r"(a0), "r"(a1), "r"(a2), "r"(a3), "r"(b0), "r"(b1));
    }
    c0 = d0; c2 = d2;
}

// fp32 warp dot (proj kernel only)
__device__ __forceinline__ float warp_dot(const float4* __restrict__ w,
                                          const float4* __restrict__ sh,
                                          int lane) {
    float ax = 0.f, ay = 0.f, az = 0.f, aw = 0.f;
#pragma unroll
    for (int k = 0; k < 16; k++) {
        float4 wv = w[k * 32 + lane];
        float4 hv = sh[k * 32 + lane];
        ax += wv.x * hv.x; ay += wv.y * hv.y;
        az += wv.z * hv.z; aw += wv.w * hv.w;
    }
    return wreduce((ax + ay) + (az + aw));
}

// ---------------- kernel 0: fp32 -> fp16 weight conversion -------------------
__global__ void cvt_kernel(const float* __restrict__ A,
                           const float* __restrict__ B,
                           const float* __restrict__ C) {
    size_t n4 = WELEM / 4;
    size_t stride = (size_t)gridDim.x * blockDim.x;
    for (size_t i = (size_t)blockIdx.x * blockDim.x + threadIdx.x; i < n4; i += stride) {
        float4 a = ((const float4*)A)[i];
        float4 b = ((const float4*)B)[i];
        float4 c = ((const float4*)C)[i];
        ((__half2*)g_whh1)[2*i]   = __floats2half2_rn(a.x, a.y);
        ((__half2*)g_whh1)[2*i+1] = __floats2half2_rn(a.z, a.w);
        ((__half2*)g_wih2)[2*i]   = __floats2half2_rn(b.x, b.y);
        ((__half2*)g_wih2)[2*i+1] = __floats2half2_rn(b.z, b.w);
        ((__half2*)g_whh2)[2*i]   = __floats2half2_rn(c.x, c.y);
        ((__half2*)g_whh2)[2*i+1] = __floats2half2_rn(c.z, c.w);
    }
}

// ---------------- kernel 1: pre1[t][row] = b1 + W_ih1[row,:] @ y[t,:] --------
__global__ void pre1_kernel(const float* __restrict__ y,
                            const float* __restrict__ W_ih1,
                            const float* __restrict__ b_ih1,
                            const float* __restrict__ b_hh1) {
    __shared__ float sy[64 * Dd];
    int row = blockIdx.x * 128 + threadIdx.x;
    int t0 = blockIdx.y * 64;
    for (int i = threadIdx.x; i < 64 * Dd; i += 128)
        sy[i] = y[(size_t)t0 * Dd + i];
    __syncthreads();

    float w[Dd];
#pragma unroll
    for (int k = 0; k < Dd; k++) w[k] = W_ih1[(size_t)row * Dd + k];
    float b = b_ih1[row] + b_hh1[row];

    for (int tt = 0; tt < 64; tt++) {
        float acc = b;
#pragma unroll
        for (int k = 0; k < Dd; k++) acc += w[k] * sy[tt * Dd + k];
        __stcs(&g_pre1[(size_t)(t0 + tt) * G4H + row], __float2half_rn(acc));
    }
}

// ---------------- kernel 2: persistent fused LSTM (1 barrier / step) ---------
// Dot engine = tensor-core mma.sync (m16n8k16, f32 accum). 12 warp-tasks:
//   tasks 0-3: W_ih2 tiles x h1   (tile 0 pinned in smem, slot 2)
//   tasks 4-7: W_hh2 tiles x h2
//   tasks 8-11: W_hh1 tiles x h1  (tiles 0,1 pinned, slots 0,1)
// Each tile = 16 gate rows (unit-major lr = 4*j+q), padded/clamped to nj.
__global__ void __launch_bounds__(NTHR, 1)
lstm_kernel(const float* __restrict__ b_ih2,
            const float* __restrict__ b_hh2) {
    extern __shared__ __half pswei[];   // 3 pinned tiles [slot][16][PROW]
    __shared__ __half sAh[Hh];      // h1[t] fp16
    __shared__ __half sBh[Hh];      // h2[t-1] fp16
    __shared__ float sg1[64];
    __shared__ float sg2[2][64];
    __shared__ float sbias[64];
    __shared__ float spre[64];
    __shared__ float sc1[16];
    __shared__ float sc2[16];

    const int tid  = threadIdx.x;
    const int lane = tid & 31;
    const int warp = tid >> 5;
    const int b    = blockIdx.x;

    const int base  = Hh / NBLK;          // 13
    const int extra = Hh % NBLK;          // 124
    const int nj = base + (b < extra ? 1 : 0);
    const int j0 = b * base + (b < extra ? b : extra);

    unsigned bgen = g_release;

    // pin 3 tiles: slot0 = W_hh1 tile0, slot1 = W_hh1 tile1, slot2 = W_ih2 tile0
    for (int i = tid; i < 3 * 16 * 256; i += NTHR) {    // 256 uint4 per row
        int s   = i / (16 * 256);
        int rem = i - s * (16 * 256);
        int r   = rem >> 8;
        int seg = rem & 255;
        const __half* src = (s == 2) ? g_wih2 : g_whh1;
        int lr = ((s == 1) ? 16 : 0) + r;
        int j = lr >> 2, q = lr & 3;                    // j <= 7 < nj always
        ((uint4*)(pswei + (size_t)(s * 16 + r) * PROW))[seg] =
            ((const uint4*)(src + ((size_t)q * Hh + j0 + j) * Hh))[seg];
    }

    for (int j = tid; j < nj; j += NTHR) g_h2[0][j0 + j] = 0.f;
    for (int r = tid; r < 4 * nj; r += NTHR) {
        int j = r >> 2, q = r & 3;
        sbias[r] = b_ih2[q * Hh + j0 + j] + b_hh2[q * Hh + j0 + j];
    }
    if (tid < 16) { sc1[tid] = 0.f; sc2[tid] = 0.f; }
    __syncthreads();

    // prologue: h1[0] = cell1(x0, 0, 0)
    if (tid < nj) {
        size_t pb = (size_t)j0 + tid;
        float gi = sigf (__half2float(__ldcs(&g_pre1[pb])));
        float gg = tanhf(__half2float(__ldcs(&g_pre1[pb + 2 * Hh])));
        float go = sigf (__half2float(__ldcs(&g_pre1[pb + 3 * Hh])));
        float c = gi * gg;
        sc1[tid] = c;
        g_h1[0][j0 + tid] = go * tanhf(c);
    }
    gbar(++bgen);

    for (int t = 0; t < Tt; t++) {
        const int p = t & 1;
        const bool last = (t == Tt - 1);

        // prefetch pre1[t+1] (latency hidden under the MMA round)
        if (!last && tid < 64) {
            int q = tid >> 4, jj = tid & 15;
            if (jj < nj)
                spre[jj * 4 + q] = __half2float(
                    __ldcs(&g_pre1[(size_t)(t + 1) * G4H + q * Hh + j0 + jj]));
        }
        // stage h1[t], h2[t-1] as fp16
        for (int i = tid; i < Hh / 4; i += NTHR) {
            float4 v = ((const float4*)g_h1[p])[i];
            ((__half2*)sAh)[2*i]   = __floats2half2_rn(v.x, v.y);
            ((__half2*)sAh)[2*i+1] = __floats2half2_rn(v.z, v.w);
            float4 w = ((const float4*)g_h2[p])[i];
            ((__half2*)sBh)[2*i]   = __floats2half2_rn(w.x, w.y);
            ((__half2*)sBh)[2*i+1] = __floats2half2_rn(w.z, w.w);
        }
        __syncthreads();

        // ---- single MMA round: 12 tasks on warps 0-11 ----
        if (warp < 12 && !(last && warp >= 8)) {
            const int g = lane >> 2, tig = lane & 3;
            const int tau = (warp < 4) ? warp : (warp < 8) ? warp - 4 : warp - 8;
            float c0, c2;
            if (warp == 0 || warp == 8 || warp == 9) {
                // pinned tiles (all use h1 = sAh)
                int s = (warp == 0) ? 2 : warp - 8;
                mma_dot(pswei + (size_t)(s * 16 + g) * PROW,
                        pswei + (size_t)(s * 16 + g + 8) * PROW,
                        sAh, g, tig, c0, c2);
            } else {
                const __half* mat = (warp < 4) ? g_wih2 : (warp < 8) ? g_whh2 : g_whh1;
                const __half* hv  = (warp >= 4 && warp < 8) ? sBh : sAh;
                int lrlo = tau * 16 + g, lrhi = lrlo + 8;
                int jlo = min(lrlo >> 2, nj - 1), jhi = min(lrhi >> 2, nj - 1);
                mma_dot(mat + ((size_t)(lrlo & 3) * Hh + j0 + jlo) * Hh,
                        mat + ((size_t)(lrhi & 3) * Hh + j0 + jhi) * Hh,
                        hv, g, tig, c0, c2);
            }
            if (tig == 0) {
                float* dst = (warp < 4) ? sg2[0] : (warp < 8) ? sg2[1] : sg1;
                int lrlo = tau * 16 + g, lrhi = lrlo + 8;
                if (lrlo < 4 * nj) dst[lrlo] = c0;
                if (lrhi < 4 * nj) dst[lrhi] = c2;
            }
        }
        __syncthreads();

        if (tid < nj) {
            float gi = sigf (sg2[0][tid*4+0] + sg2[1][tid*4+0] + sbias[tid*4+0]);
            float gf = sigf (sg2[0][tid*4+1] + sg2[1][tid*4+1] + sbias[tid*4+1]);
            float gg = tanhf(sg2[0][tid*4+2] + sg2[1][tid*4+2] + sbias[tid*4+2]);
            float go = sigf (sg2[0][tid*4+3] + sg2[1][tid*4+3] + sbias[tid*4+3]);
            float c = gf * sc2[tid] + gi * gg;
            sc2[tid] = c;
            float hn = go * tanhf(c);
            g_h2[1 - p][j0 + tid] = hn;
            __stcs(&g_h2hist[t][j0 + tid], hn);
        } else if (tid >= 32 && tid < 32 + nj && !last) {
            int u = tid - 32;
            float gi = sigf (sg1[u*4+0] + spre[u*4+0]);
            float gf = sigf (sg1[u*4+1] + spre[u*4+1]);
            float gg = tanhf(sg1[u*4+2] + spre[u*4+2]);
            float go = sigf (sg1[u*4+3] + spre[u*4+3]);
            float c = gf * sc1[u] + gi * gg;
            sc1[u] = c;
            g_h1[1 - p][j0 + u] = go * tanhf(c);
        }
        gbar(++bgen);
    }
}

// ---------------- kernel 3: output projection --------------------------------
__global__ void proj_kernel(const float* __restrict__ W_lin,
                            const float* __restrict__ b_lin,
                            float* __restrict__ out,
                            int prelen) {
    __shared__ float sh[Hh];
    const int t = prelen + blockIdx.x;
    const int tid = threadIdx.x;
    const int lane = tid & 31;
    const int warp = tid >> 5;

    for (int i = tid; i < Hh / 4; i += 256)
        ((float4*)sh)[i] = ((const float4*)&g_h2hist[t][0])[i];
    __syncthreads();

    for (int d = warp; d < Dd; d += 8) {
        float s = warp_dot((const float4*)(W_lin + (size_t)d * Hh),
                           (const float4*)sh, lane);
        if (lane == 0) out[(size_t)blockIdx.x * Dd + d] = s + b_lin[d];
    }
}

extern "C" void kernel_launch(void* const* d_in, const int* in_sizes, int n_in,
                              void* d_out, int out_size) {
    const float* y     = (const float*)d_in[0];
    const float* W_ih1 = (const float*)d_in[1];
    const float* W_hh1 = (const float*)d_in[2];
    const float* b_ih1 = (const float*)d_in[3];
    const float* b_hh1 = (const float*)d_in[4];
    const float* W_ih2 = (const float*)d_in[5];
    const float* W_hh2 = (const float*)d_in[6];
    const float* b_ih2 = (const float*)d_in[7];
    const float* b_hh2 = (const float*)d_in[8];
    const float* W_lin = (const float*)d_in[9];
    const float* b_lin = (const float*)d_in[10];
    (void)in_sizes; (void)n_in;

    const int nt = out_size / Dd;
    const int prelen = Tt - nt;

    cudaFuncSetAttribute(lstm_kernel,
                         cudaFuncAttributeMaxDynamicSharedMemorySize,
                         (int)SWBYTES);

    cvt_kernel<<<2048, 256>>>(W_hh1, W_ih2, W_hh2);
    dim3 g1(G4H / 128, Tt / 64);
    pre1_kernel<<<g1, 128>>>(y, W_ih1, b_ih1, b_hh1);
    lstm_kernel<<<NBLK, NTHR, SWBYTES>>>(b_ih2, b_hh2);
    proj_kernel<<<nt, 256>>>(W_lin, b_lin, (float*)d_out, prelen);
}

// round 11
// speedup vs baseline: 1.5420x; 1.5420x over previous
#include <cuda_runtime.h>
#include <cuda_fp16.h>
#include <math.h>

#define Hh 2048
#define Tt 4096
#define Dd 66
#define G4H (4*Hh)
#define NBLK 148
#define NTHR 512
#define NWARP (NTHR/32)
#define NJMAX 14
#define WELEM ((size_t)G4H*(size_t)Hh)
#define WSTRIDE ((size_t)Hh*(size_t)Hh)
// pinned: 3*nj rows W_hh1 (i,f,g) + 8 rows W_hh2 (units 0,1 all gates)
#define SWBYTES ((3*NJMAX + 8)*Hh*sizeof(__half))   // 204800 B

// ---------------- persistent device state (static; no runtime allocs) -------
__device__ float  g_h1[2][Hh];
__device__ float  g_h2[2][Hh];
__device__ float  g_h2hist[Tt][Hh];                // 33.5 MB
__device__ __half g_pre1[(size_t)Tt * G4H];        // 67 MB fp16 (streamed, .cs)
__device__ __half g_whh1[WELEM];                   // 33.5 MB fp16
__device__ __half g_wih2[WELEM];
__device__ __half g_whh2[WELEM];

// flag barrier state (monotonic across graph replays)
__device__ volatile unsigned g_arrive[NBLK];

__device__ __forceinline__ float sigf(float x) { return 1.0f / (1.0f + expf(-x)); }

// ---------------- split all-poll grid barrier --------------------------------
// arrive: publish this block's monotonically-increasing counter.
// wait:   threads 0..147 each poll one block's flag; no central release leg.
__device__ __forceinline__ void gbar_arrive(unsigned target) {
    __syncthreads();
    if (threadIdx.x == 0) {
        __threadfence();
        g_arrive[blockIdx.x] = target;
    }
}
__device__ __forceinline__ void gbar_wait(unsigned target) {
    if (threadIdx.x < NBLK) {
        while ((int)(g_arrive[threadIdx.x] - target) < 0) { }
        __threadfence();
    }
    __syncthreads();
}

// ---------------- helpers ----------------------------------------------------
__device__ __forceinline__ float wreduce(float s) {
#pragma unroll
    for (int o = 16; o; o >>= 1) s += __shfl_down_sync(0xffffffffu, s, o);
    return s;
}

__device__ __forceinline__ unsigned long long cvt_h2_f2(unsigned h2) {
    unsigned long long r;
    asm("{\n\t"
        ".reg .f16 h0, h1;\n\t"
        ".reg .f32 f0, f1;\n\t"
        "mov.b32 {h0, h1}, %1;\n\t"
        "cvt.f32.f16 f0, h0;\n\t"
        "cvt.f32.f16 f1, h1;\n\t"
        "mov.b64 %0, {f0, f1};\n\t"
        "}" : "=l"(r) : "r"(h2));
    return r;
}

__device__ __forceinline__ void fma2(unsigned long long& acc,
                                     unsigned long long a,
                                     unsigned long long b) {
    asm("fma.rn.f32x2 %0, %1, %2, %3;" : "=l"(acc) : "l"(a), "l"(b), "l"(acc));
}

__device__ __forceinline__ float accsum(unsigned long long a) {
    float lo, hi;
    asm("mov.b64 {%0, %1}, %2;" : "=f"(lo), "=f"(hi) : "l"(a));
    return lo + hi;
}

__device__ __forceinline__ void du4p(uint4 w, ulonglong2 h0, ulonglong2 h1,
                                     unsigned long long& acc) {
    fma2(acc, cvt_h2_f2(w.x), h0.x);
    fma2(acc, cvt_h2_f2(w.y), h0.y);
    fma2(acc, cvt_h2_f2(w.z), h1.x);
    fma2(acc, cvt_h2_f2(w.w), h1.y);
}

// 4 gate rows streaming from global; first iteration's weights preloaded
// across the barrier in pf0..pf3 (16 regs).
__device__ __forceinline__ float4 dot4g_pf(const __half* __restrict__ w0,
                                           const ulonglong2* __restrict__ hv, int lane,
                                           uint4 f0, uint4 f1, uint4 f2, uint4 f3) {
    const uint4* p0 = (const uint4*)w0;
    const uint4* p1 = (const uint4*)(w0 + WSTRIDE);
    const uint4* p2 = (const uint4*)(w0 + 2 * WSTRIDE);
    const uint4* p3 = (const uint4*)(w0 + 3 * WSTRIDE);
    unsigned long long a0 = 0ull, a1 = 0ull, a2 = 0ull, a3 = 0ull;
    {   // k = 0 from prefetched registers
        ulonglong2 h0 = hv[2 * lane], h1 = hv[2 * lane + 1];
        du4p(f0, h0, h1, a0);
        du4p(f1, h0, h1, a1);
        du4p(f2, h0, h1, a2);
        du4p(f3, h0, h1, a3);
    }
#pragma unroll 2
    for (int k = 1; k < 8; k++) {
        int idx = k * 32 + lane;
        ulonglong2 h0 = hv[2 * idx], h1 = hv[2 * idx + 1];
        du4p(p0[idx], h0, h1, a0);
        du4p(p1[idx], h0, h1, a1);
        du4p(p2[idx], h0, h1, a2);
        du4p(p3[idx], h0, h1, a3);
    }
    return make_float4(wreduce(accsum(a0)), wreduce(accsum(a1)),
                       wreduce(accsum(a2)), wreduce(accsum(a3)));
}

// 4 gate rows, all streaming (no prefetch)
__device__ __forceinline__ float4 dot4g(const __half* __restrict__ w0,
                                        const ulonglong2* __restrict__ hv, int lane) {
    const uint4* p0 = (const uint4*)w0;
    const uint4* p1 = (const uint4*)(w0 + WSTRIDE);
    const uint4* p2 = (const uint4*)(w0 + 2 * WSTRIDE);
    const uint4* p3 = (const uint4*)(w0 + 3 * WSTRIDE);
    unsigned long long a0 = 0ull, a1 = 0ull, a2 = 0ull, a3 = 0ull;
#pragma unroll 2
    for (int k = 0; k < 8; k++) {
        int idx = k * 32 + lane;
        ulonglong2 h0 = hv[2 * idx], h1 = hv[2 * idx + 1];
        du4p(p0[idx], h0, h1, a0);
        du4p(p1[idx], h0, h1, a1);
        du4p(p2[idx], h0, h1, a2);
        du4p(p3[idx], h0, h1, a3);
    }
    return make_float4(wreduce(accsum(a0)), wreduce(accsum(a1)),
                       wreduce(accsum(a2)), wreduce(accsum(a3)));
}

// 4 gate rows from explicit pointers (smem and/or global; resolved at each
// inlined call site).
__device__ __forceinline__ float4 dot_pin(const __half* si, const __half* sf,
                                          const __half* sg,
                                          const __half* wo,
                                          const ulonglong2* __restrict__ hv, int lane) {
    const uint4* pi = (const uint4*)si;
    const uint4* pf = (const uint4*)sf;
    const uint4* pg = (const uint4*)sg;
    const uint4* po = (const uint4*)wo;
    unsigned long long a0 = 0ull, a1 = 0ull, a2 = 0ull, a3 = 0ull;
#pragma unroll 2
    for (int k = 0; k < 8; k++) {
        int idx = k * 32 + lane;
        ulonglong2 h0 = hv[2 * idx], h1 = hv[2 * idx + 1];
        du4p(pi[idx], h0, h1, a0);
        du4p(pf[idx], h0, h1, a1);
        du4p(pg[idx], h0, h1, a2);
        du4p(po[idx], h0, h1, a3);
    }
    return make_float4(wreduce(accsum(a0)), wreduce(accsum(a1)),
                       wreduce(accsum(a2)), wreduce(accsum(a3)));
}

// fp32 warp dot (proj kernel only)
__device__ __forceinline__ float warp_dot(const float4* __restrict__ w,
                                          const float4* __restrict__ sh,
                                          int lane) {
    float ax = 0.f, ay = 0.f, az = 0.f, aw = 0.f;
#pragma unroll
    for (int k = 0; k < 16; k++) {
        float4 wv = w[k * 32 + lane];
        float4 hv = sh[k * 32 + lane];
        ax += wv.x * hv.x; ay += wv.y * hv.y;
        az += wv.z * hv.z; aw += wv.w * hv.w;
    }
    return wreduce((ax + ay) + (az + aw));
}

// ---------------- kernel 0: fp32 -> fp16 weight conversion -------------------
__global__ void cvt_kernel(const float* __restrict__ A,
                           const float* __restrict__ B,
                           const float* __restrict__ C) {
    size_t n4 = WELEM / 4;
    size_t stride = (size_t)gridDim.x * blockDim.x;
    for (size_t i = (size_t)blockIdx.x * blockDim.x + threadIdx.x; i < n4; i += stride) {
        float4 a = ((const float4*)A)[i];
        float4 b = ((const float4*)B)[i];
        float4 c = ((const float4*)C)[i];
        ((__half2*)g_whh1)[2*i]   = __floats2half2_rn(a.x, a.y);
        ((__half2*)g_whh1)[2*i+1] = __floats2half2_rn(a.z, a.w);
        ((__half2*)g_wih2)[2*i]   = __floats2half2_rn(b.x, b.y);
        ((__half2*)g_wih2)[2*i+1] = __floats2half2_rn(b.z, b.w);
        ((__half2*)g_whh2)[2*i]   = __floats2half2_rn(c.x, c.y);
        ((__half2*)g_whh2)[2*i+1] = __floats2half2_rn(c.z, c.w);
    }
}

// ---------------- kernel 1: pre1[t][row] = b1 + W_ih1[row,:] @ y[t,:] --------
__global__ void pre1_kernel(const float* __restrict__ y,
                            const float* __restrict__ W_ih1,
                            const float* __restrict__ b_ih1,
                            const float* __restrict__ b_hh1) {
    __shared__ float sy[64 * Dd];
    int row = blockIdx.x * 128 + threadIdx.x;
    int t0 = blockIdx.y * 64;
    for (int i = threadIdx.x; i < 64 * Dd; i += 128)
        sy[i] = y[(size_t)t0 * Dd + i];
    __syncthreads();

    float w[Dd];
#pragma unroll
    for (int k = 0; k < Dd; k++) w[k] = W_ih1[(size_t)row * Dd + k];
    float b = b_ih1[row] + b_hh1[row];

    for (int tt = 0; tt < 64; tt++) {
        float acc = b;
#pragma unroll
        for (int k = 0; k < Dd; k++) acc += w[k] * sy[tt * Dd + k];
        __stcs(&g_pre1[(size_t)(t0 + tt) * G4H + row], __float2half_rn(acc));
    }
}

// ---------------- kernel 2: persistent fused LSTM (1 split-barrier / step) ---
// Pinned in smem: W_hh1 gates i/f/g (3*nj rows) + W_hh2 units 0,1 (8 rows).
// Round-0 streamed tasks (W_ih2, task==warp) prefetch their first weight
// iteration across the barrier window.
__global__ void __launch_bounds__(NTHR, 1)
lstm_kernel(const float* __restrict__ b_ih2,
            const float* __restrict__ b_hh2) {
    extern __shared__ __half swei[];   // [3*nj + 8][Hh]
    __shared__ float sA[Hh];        // h1[t]
    __shared__ float sB[Hh];        // h2[t-1]
    __shared__ float sg1[64];
    __shared__ float sg2[2][64];
    __shared__ float sbias[64];
    __shared__ float spre[64];
    __shared__ float sc1[16];
    __shared__ float sc2[16];

    const int tid  = threadIdx.x;
    const int lane = tid & 31;
    const int warp = tid >> 5;
    const int b    = blockIdx.x;

    const int base  = Hh / NBLK;          // 13
    const int extra = Hh % NBLK;          // 124
    const int nj = base + (b < extra ? 1 : 0);
    const int j0 = b * base + (b < extra ? b : extra);

    unsigned bgen = g_arrive[blockIdx.x];   // monotonic base for this launch

    // pin W_hh1 i,f,g rows + W_hh2 units 0,1 into smem (coalesced, one-time)
    const int segs = Hh / 8;               // 256 uint4 per row
    const int prows = 3 * nj + 8;
    for (int i = tid; i < prows * segs; i += NTHR) {
        int row = i / segs;
        int seg = i - row * segs;
        const __half* src;
        if (row < 3 * nj) {
            int g = row / nj, j = row - g * nj;
            src = g_whh1 + ((size_t)g * Hh + j0 + j) * Hh;
        } else {
            int rr = row - 3 * nj;
            int j = rr >> 2, q = rr & 3;
            src = g_whh2 + ((size_t)q * Hh + j0 + j) * Hh;
        }
        ((uint4*)(swei + (size_t)row * Hh))[seg] = ((const uint4*)src)[seg];
    }

    for (int j = tid; j < nj; j += NTHR) g_h2[0][j0 + j] = 0.f;
    for (int r = tid; r < 4 * nj; r += NTHR) {
        int j = r >> 2, q = r & 3;
        sbias[r] = b_ih2[q * Hh + j0 + j] + b_hh2[q * Hh + j0 + j];
    }
    if (tid < 16) { sc1[tid] = 0.f; sc2[tid] = 0.f; }
    __syncthreads();

    // prologue: h1[0] = cell1(x0, 0, 0)
    if (tid < nj) {
        size_t pb = (size_t)j0 + tid;
        float gi = sigf (__half2float(__ldcs(&g_pre1[pb])));
        float gg = tanhf(__half2float(__ldcs(&g_pre1[pb + 2 * Hh])));
        float go = sigf (__half2float(__ldcs(&g_pre1[pb + 3 * Hh])));
        float c = gi * gg;
        sc1[tid] = c;
        g_h1[0][j0 + tid] = go * tanhf(c);
    }

    uint4 pf0 = {0,0,0,0}, pf1 = {0,0,0,0}, pf2 = {0,0,0,0}, pf3 = {0,0,0,0};
    const __half* pfbase = g_wih2 + (size_t)(j0 + warp) * Hh;

    gbar_arrive(++bgen);
    if (warp < nj) {    // prefetch round-0 task first iteration during barrier
        pf0 = ((const uint4*)pfbase)[lane];
        pf1 = ((const uint4*)(pfbase + WSTRIDE))[lane];
        pf2 = ((const uint4*)(pfbase + 2 * WSTRIDE))[lane];
        pf3 = ((const uint4*)(pfbase + 3 * WSTRIDE))[lane];
    }
    gbar_wait(bgen);

    for (int t = 0; t < Tt; t++) {
        const int p = t & 1;
        const bool last = (t == Tt - 1);

        if (!last && tid < 64) {
            int q = tid >> 4, jj = tid & 15;
            if (jj < nj)
                spre[jj * 4 + q] = __half2float(
                    __ldcs(&g_pre1[(size_t)(t + 1) * G4H + q * Hh + j0 + jj]));
        }
        for (int i = tid; i < Hh / 4; i += NTHR)
            ((float4*)sA)[i] = ((const float4*)g_h1[p])[i];
        for (int i = tid; i < Hh / 4; i += NTHR)
            ((float4*)sB)[i] = ((const float4*)g_h2[p])[i];
        __syncthreads();

        const int ntask = last ? 2 * nj : 3 * nj;
        for (int task = warp; task < ntask; task += NWARP) {
            if (task < nj) {
                // W_ih2, round-0 (task == warp always here): use prefetch
                float4 r = dot4g_pf(g_wih2 + (size_t)(j0 + task) * Hh,
                                    (const ulonglong2*)sA, lane, pf0, pf1, pf2, pf3);
                if (lane == 0) {
                    float* dst = &sg2[0][task * 4];
                    dst[0] = r.x; dst[1] = r.y; dst[2] = r.z; dst[3] = r.w;
                }
            } else if (task < nj + 2) {
                // W_hh2 units 0,1: fully smem-pinned
                int j = task - nj;
                const __half* s0 = swei + (size_t)(3 * nj + j * 4) * Hh;
                float4 r = dot_pin(s0, s0 + Hh, s0 + 2 * Hh, s0 + 3 * Hh,
                                   (const ulonglong2*)sB, lane);
                if (lane == 0) {
                    float* dst = &sg2[1][j * 4];
                    dst[0] = r.x; dst[1] = r.y; dst[2] = r.z; dst[3] = r.w;
                }
            } else if (task < 2 * nj) {
                int j = task - nj;
                float4 r = dot4g(g_whh2 + (size_t)(j0 + j) * Hh,
                                 (const ulonglong2*)sB, lane);
                if (lane == 0) {
                    float* dst = &sg2[1][j * 4];
                    dst[0] = r.x; dst[1] = r.y; dst[2] = r.z; dst[3] = r.w;
                }
            } else {
                int j = task - 2 * nj;
                float4 r = dot_pin(swei + (size_t)j * Hh,
                                   swei + (size_t)(nj + j) * Hh,
                                   swei + (size_t)(2 * nj + j) * Hh,
                                   g_whh1 + ((size_t)3 * Hh + j0 + j) * Hh,
                                   (const ulonglong2*)sA, lane);
                if (lane == 0) {
                    sg1[j * 4 + 0] = r.x; sg1[j * 4 + 1] = r.y;
                    sg1[j * 4 + 2] = r.z; sg1[j * 4 + 3] = r.w;
                }
            }
        }
        __syncthreads();

        if (tid < nj) {
            float gi = sigf (sg2[0][tid*4+0] + sg2[1][tid*4+0] + sbias[tid*4+0]);
            float gf = sigf (sg2[0][tid*4+1] + sg2[1][tid*4+1] + sbias[tid*4+1]);
            float gg = tanhf(sg2[0][tid*4+2] + sg2[1][tid*4+2] + sbias[tid*4+2]);
            float go = sigf (sg2[0][tid*4+3] + sg2[1][tid*4+3] + sbias[tid*4+3]);
            float c = gf * sc2[tid] + gi * gg;
            sc2[tid] = c;
            float hn = go * tanhf(c);
            g_h2[1 - p][j0 + tid] = hn;
            __stcs(&g_h2hist[t][j0 + tid], hn);
        } else if (tid >= 32 && tid < 32 + nj && !last) {
            int u = tid - 32;
            float gi = sigf (sg1[u*4+0] + spre[u*4+0]);
            float gf = sigf (sg1[u*4+1] + spre[u*4+1]);
            float gg = tanhf(sg1[u*4+2] + spre[u*4+2]);
            float go = sigf (sg1[u*4+3] + spre[u*4+3]);
            float c = gf * sc1[u] + gi * gg;
            sc1[u] = c;
            g_h1[1 - p][j0 + u] = go * tanhf(c);
        }

        gbar_arrive(++bgen);
        if (warp < nj) {    // prefetch next step's round-0 weights during barrier
            pf0 = ((const uint4*)pfbase)[lane];
            pf1 = ((const uint4*)(pfbase + WSTRIDE))[lane];
            pf2 = ((const uint4*)(pfbase + 2 * WSTRIDE))[lane];
            pf3 = ((const uint4*)(pfbase + 3 * WSTRIDE))[lane];
        }
        gbar_wait(bgen);
    }
}

// ---------------- kernel 3: output projection --------------------------------
__global__ void proj_kernel(const float* __restrict__ W_lin,
                            const float* __restrict__ b_lin,
                            float* __restrict__ out,
                            int prelen) {
    __shared__ float sh[Hh];
    const int t = prelen + blockIdx.x;
    const int tid = threadIdx.x;
    const int lane = tid & 31;
    const int warp = tid >> 5;

    for (int i = tid; i < Hh / 4; i += 256)
        ((float4*)sh)[i] = ((const float4*)&g_h2hist[t][0])[i];
    __syncthreads();

    for (int d = warp; d < Dd; d += 8) {
        float s = warp_dot((const float4*)(W_lin + (size_t)d * Hh),
                           (const float4*)sh, lane);
        if (lane == 0) out[(size_t)blockIdx.x * Dd + d] = s + b_lin[d];
    }
}

extern "C" void kernel_launch(void* const* d_in, const int* in_sizes, int n_in,
                              void* d_out, int out_size) {
    const float* y     = (const float*)d_in[0];
    const float* W_ih1 = (const float*)d_in[1];
    const float* W_hh1 = (const float*)d_in[2];
    const float* b_ih1 = (const float*)d_in[3];
    const float* b_hh1 = (const float*)d_in[4];
    const float* W_ih2 = (const float*)d_in[5];
    const float* W_hh2 = (const float*)d_in[6];
    const float* b_ih2 = (const float*)d_in[7];
    const float* b_hh2 = (const float*)d_in[8];
    const float* W_lin = (const float*)d_in[9];
    const float* b_lin = (const float*)d_in[10];
    (void)in_sizes; (void)n_in;

    const int nt = out_size / Dd;
    const int prelen = Tt - nt;

    cudaFuncSetAttribute(lstm_kernel,
                         cudaFuncAttributeMaxDynamicSharedMemorySize,
                         (int)SWBYTES);

    cvt_kernel<<<2048, 256>>>(W_hh1, W_ih2, W_hh2);
    dim3 g1(G4H / 128, Tt / 64);
    pre1_kernel<<<g1, 128>>>(y, W_ih1, b_ih1, b_hh1);
    lstm_kernel<<<NBLK, NTHR, SWBYTES>>>(b_ih2, b_hh2);
    proj_kernel<<<nt, 256>>>(W_lin, b_lin, (float*)d_out, prelen);
}

// round 12
// speedup vs baseline: 2.2720x; 1.4734x over previous
#include <cuda_runtime.h>
#include <cuda_fp16.h>
#include <math.h>

#define Hh 2048
#define Tt 4096
#define Dd 66
#define G4H (4*Hh)
#define NBLK 148
#define NTHR 512
#define NWARP (NTHR/32)
#define NJMAX 14
#define WELEM ((size_t)G4H*(size_t)Hh)
#define WSTRIDE ((size_t)Hh*(size_t)Hh)
// pinned: 3*nj rows W_hh1 (i,f,g) + 8 rows W_hh2 (units 0,1 all gates)
#define SWBYTES ((3*NJMAX + 8)*Hh*sizeof(__half))   // 204800 B

// ---------------- persistent device state (static; no runtime allocs) -------
__device__ float  g_h1[2][Hh];
__device__ float  g_h2[2][Hh];
__device__ float  g_h2hist[Tt][Hh];                // 33.5 MB
__device__ __half g_pre1[(size_t)Tt * G4H];        // 67 MB fp16 (streamed, .cs)
__device__ __half g_whh1[WELEM];                   // 33.5 MB fp16
__device__ __half g_wih2[WELEM];
__device__ __half g_whh2[WELEM];

// flag barrier state (monotonic across graph replays) — R6 central-release
__device__ volatile unsigned g_arrive[NBLK];
__device__ volatile unsigned g_release;

__device__ __forceinline__ float sigf(float x) { return 1.0f / (1.0f + expf(-x)); }

// ---------------- split central-release grid barrier (R6 semantics) ----------
__device__ __forceinline__ void gbar_arrive(unsigned target) {
    __syncthreads();
    if (blockIdx.x != 0 && threadIdx.x == 0) {
        __threadfence();
        g_arrive[blockIdx.x] = target;
    }
}
__device__ __forceinline__ void gbar_wait(unsigned target) {
    if (blockIdx.x == 0) {
        if (threadIdx.x > 0 && threadIdx.x < NBLK) {
            while ((int)(g_arrive[threadIdx.x] - target) < 0) { }
        }
        __syncthreads();
        if (threadIdx.x == 0) { __threadfence(); g_release = target; }
    } else {
        if (threadIdx.x == 0) {
            while ((int)(g_release - target) < 0) { }
            __threadfence();
        }
    }
    __syncthreads();
}

// ---------------- helpers ----------------------------------------------------
__device__ __forceinline__ float wreduce(float s) {
#pragma unroll
    for (int o = 16; o; o >>= 1) s += __shfl_down_sync(0xffffffffu, s, o);
    return s;
}

__device__ __forceinline__ unsigned long long cvt_h2_f2(unsigned h2) {
    unsigned long long r;
    asm("{\n\t"
        ".reg .f16 h0, h1;\n\t"
        ".reg .f32 f0, f1;\n\t"
        "mov.b32 {h0, h1}, %1;\n\t"
        "cvt.f32.f16 f0, h0;\n\t"
        "cvt.f32.f16 f1, h1;\n\t"
        "mov.b64 %0, {f0, f1};\n\t"
        "}" : "=l"(r) : "r"(h2));
    return r;
}

__device__ __forceinline__ void fma2(unsigned long long& acc,
                                     unsigned long long a,
                                     unsigned long long b) {
    asm("fma.rn.f32x2 %0, %1, %2, %3;" : "=l"(acc) : "l"(a), "l"(b), "l"(acc));
}

__device__ __forceinline__ float accsum(unsigned long long a) {
    float lo, hi;
    asm("mov.b64 {%0, %1}, %2;" : "=f"(lo), "=f"(hi) : "l"(a));
    return lo + hi;
}

__device__ __forceinline__ void du4p(uint4 w, ulonglong2 h0, ulonglong2 h1,
                                     unsigned long long& acc) {
    fma2(acc, cvt_h2_f2(w.x), h0.x);
    fma2(acc, cvt_h2_f2(w.y), h0.y);
    fma2(acc, cvt_h2_f2(w.z), h1.x);
    fma2(acc, cvt_h2_f2(w.w), h1.y);
}

// 4 gate rows streaming; k=0 comes from prefetched regs (loaded in barrier window)
__device__ __forceinline__ float4 dot4g_pf(const __half* __restrict__ w0,
                                           const ulonglong2* __restrict__ hv, int lane,
                                           uint4 f0, uint4 f1, uint4 f2, uint4 f3) {
    const uint4* p0 = (const uint4*)w0;
    const uint4* p1 = (const uint4*)(w0 + WSTRIDE);
    const uint4* p2 = (const uint4*)(w0 + 2 * WSTRIDE);
    const uint4* p3 = (const uint4*)(w0 + 3 * WSTRIDE);
    unsigned long long a0 = 0ull, a1 = 0ull, a2 = 0ull, a3 = 0ull;
    {
        ulonglong2 h0 = hv[2 * lane], h1 = hv[2 * lane + 1];
        du4p(f0, h0, h1, a0);
        du4p(f1, h0, h1, a1);
        du4p(f2, h0, h1, a2);
        du4p(f3, h0, h1, a3);
    }
#pragma unroll 2
    for (int k = 1; k < 8; k++) {
        int idx = k * 32 + lane;
        ulonglong2 h0 = hv[2 * idx], h1 = hv[2 * idx + 1];
        du4p(p0[idx], h0, h1, a0);
        du4p(p1[idx], h0, h1, a1);
        du4p(p2[idx], h0, h1, a2);
        du4p(p3[idx], h0, h1, a3);
    }
    return make_float4(wreduce(accsum(a0)), wreduce(accsum(a1)),
                       wreduce(accsum(a2)), wreduce(accsum(a3)));
}

// 4 gate rows, all streaming
__device__ __forceinline__ float4 dot4g(const __half* __restrict__ w0,
                                        const ulonglong2* __restrict__ hv, int lane) {
    const uint4* p0 = (const uint4*)w0;
    const uint4* p1 = (const uint4*)(w0 + WSTRIDE);
    const uint4* p2 = (const uint4*)(w0 + 2 * WSTRIDE);
    const uint4* p3 = (const uint4*)(w0 + 3 * WSTRIDE);
    unsigned long long a0 = 0ull, a1 = 0ull, a2 = 0ull, a3 = 0ull;
#pragma unroll 2
    for (int k = 0; k < 8; k++) {
        int idx = k * 32 + lane;
        ulonglong2 h0 = hv[2 * idx], h1 = hv[2 * idx + 1];
        du4p(p0[idx], h0, h1, a0);
        du4p(p1[idx], h0, h1, a1);
        du4p(p2[idx], h0, h1, a2);
        du4p(p3[idx], h0, h1, a3);
    }
    return make_float4(wreduce(accsum(a0)), wreduce(accsum(a1)),
                       wreduce(accsum(a2)), wreduce(accsum(a3)));
}

// 4 gate rows from explicit pointers (smem and/or global)
__device__ __forceinline__ float4 dot_pin(const __half* si, const __half* sf,
                                          const __half* sg,
                                          const __half* wo,
                                          const ulonglong2* __restrict__ hv, int lane) {
    const uint4* pi = (const uint4*)si;
    const uint4* pf = (const uint4*)sf;
    const uint4* pg = (const uint4*)sg;
    const uint4* po = (const uint4*)wo;
    unsigned long long a0 = 0ull, a1 = 0ull, a2 = 0ull, a3 = 0ull;
#pragma unroll 2
    for (int k = 0; k < 8; k++) {
        int idx = k * 32 + lane;
        ulonglong2 h0 = hv[2 * idx], h1 = hv[2 * idx + 1];
        du4p(pi[idx], h0, h1, a0);
        du4p(pf[idx], h0, h1, a1);
        du4p(pg[idx], h0, h1, a2);
        du4p(po[idx], h0, h1, a3);
    }
    return make_float4(wreduce(accsum(a0)), wreduce(accsum(a1)),
                       wreduce(accsum(a2)), wreduce(accsum(a3)));
}

// fp32 warp dot (proj kernel only)
__device__ __forceinline__ float warp_dot(const float4* __restrict__ w,
                                          const float4* __restrict__ sh,
                                          int lane) {
    float ax = 0.f, ay = 0.f, az = 0.f, aw = 0.f;
#pragma unroll
    for (int k = 0; k < 16; k++) {
        float4 wv = w[k * 32 + lane];
        float4 hv = sh[k * 32 + lane];
        ax += wv.x * hv.x; ay += wv.y * hv.y;
        az += wv.z * hv.z; aw += wv.w * hv.w;
    }
    return wreduce((ax + ay) + (az + aw));
}

// ---------------- kernel 0: fp32 -> fp16 weight conversion -------------------
__global__ void cvt_kernel(const float* __restrict__ A,
                           const float* __restrict__ B,
                           const float* __restrict__ C) {
    size_t n4 = WELEM / 4;
    size_t stride = (size_t)gridDim.x * blockDim.x;
    for (size_t i = (size_t)blockIdx.x * blockDim.x + threadIdx.x; i < n4; i += stride) {
        float4 a = ((const float4*)A)[i];
        float4 b = ((const float4*)B)[i];
        float4 c = ((const float4*)C)[i];
        ((__half2*)g_whh1)[2*i]   = __floats2half2_rn(a.x, a.y);
        ((__half2*)g_whh1)[2*i+1] = __floats2half2_rn(a.z, a.w);
        ((__half2*)g_wih2)[2*i]   = __floats2half2_rn(b.x, b.y);
        ((__half2*)g_wih2)[2*i+1] = __floats2half2_rn(b.z, b.w);
        ((__half2*)g_whh2)[2*i]   = __floats2half2_rn(c.x, c.y);
        ((__half2*)g_whh2)[2*i+1] = __floats2half2_rn(c.z, c.w);
    }
}

// ---------------- kernel 1: pre1[t][row] = b1 + W_ih1[row,:] @ y[t,:] --------
__global__ void pre1_kernel(const float* __restrict__ y,
                            const float* __restrict__ W_ih1,
                            const float* __restrict__ b_ih1,
                            const float* __restrict__ b_hh1) {
    __shared__ float sy[64 * Dd];
    int row = blockIdx.x * 128 + threadIdx.x;
    int t0 = blockIdx.y * 64;
    for (int i = threadIdx.x; i < 64 * Dd; i += 128)
        sy[i] = y[(size_t)t0 * Dd + i];
    __syncthreads();

    float w[Dd];
#pragma unroll
    for (int k = 0; k < Dd; k++) w[k] = W_ih1[(size_t)row * Dd + k];
    float b = b_ih1[row] + b_hh1[row];

    for (int tt = 0; tt < 64; tt++) {
        float acc = b;
#pragma unroll
        for (int k = 0; k < Dd; k++) acc += w[k] * sy[tt * Dd + k];
        __stcs(&g_pre1[(size_t)(t0 + tt) * G4H + row], __float2half_rn(acc));
    }
}

// ---------------- kernel 2: persistent fused LSTM (1 barrier / step) ---------
// Pinned in smem: W_hh1 gates i/f/g (3*nj rows) + W_hh2 units 0,1 (8 rows).
// W_ih2 round-0 warps prefetch their first k-iter inside the barrier window.
__global__ void __launch_bounds__(NTHR, 1)
lstm_kernel(const float* __restrict__ b_ih2,
            const float* __restrict__ b_hh2) {
    extern __shared__ __half swei[];   // [3*nj + 8][Hh]
    __shared__ float sA[Hh];        // h1[t]
    __shared__ float sB[Hh];        // h2[t-1]
    __shared__ float sg1[64];
    __shared__ float sg2[2][64];
    __shared__ float sbias[64];
    __shared__ float spre[64];
    __shared__ float sc1[16];
    __shared__ float sc2[16];

    const int tid  = threadIdx.x;
    const int lane = tid & 31;
    const int warp = tid >> 5;
    const int b    = blockIdx.x;

    const int base  = Hh / NBLK;          // 13
    const int extra = Hh % NBLK;          // 124
    const int nj = base + (b < extra ? 1 : 0);
    const int j0 = b * base + (b < extra ? b : extra);

    unsigned bgen = g_release;

    // pin W_hh1 i,f,g rows + W_hh2 units 0,1 into smem (coalesced, one-time)
    const int segs = Hh / 8;               // 256 uint4 per row
    const int prows = 3 * nj + 8;
    for (int i = tid; i < prows * segs; i += NTHR) {
        int row = i / segs;
        int seg = i - row * segs;
        const __half* src;
        if (row < 3 * nj) {
            int g = row / nj, j = row - g * nj;
            src = g_whh1 + ((size_t)g * Hh + j0 + j) * Hh;
        } else {
            int rr = row - 3 * nj;
            int j = rr >> 2, q = rr & 3;
            src = g_whh2 + ((size_t)q * Hh + j0 + j) * Hh;
        }
        ((uint4*)(swei + (size_t)row * Hh))[seg] = ((const uint4*)src)[seg];
    }

    for (int j = tid; j < nj; j += NTHR) g_h2[0][j0 + j] = 0.f;
    for (int r = tid; r < 4 * nj; r += NTHR) {
        int j = r >> 2, q = r & 3;
        sbias[r] = b_ih2[q * Hh + j0 + j] + b_hh2[q * Hh + j0 + j];
    }
    if (tid < 16) { sc1[tid] = 0.f; sc2[tid] = 0.f; }
    __syncthreads();

    // prologue: h1[0] = cell1(x0, 0, 0)
    if (tid < nj) {
        size_t pb = (size_t)j0 + tid;
        float gi = sigf (__half2float(__ldcs(&g_pre1[pb])));
        float gg = tanhf(__half2float(__ldcs(&g_pre1[pb + 2 * Hh])));
        float go = sigf (__half2float(__ldcs(&g_pre1[pb + 3 * Hh])));
        float c = gi * gg;
        sc1[tid] = c;
        g_h1[0][j0 + tid] = go * tanhf(c);
    }

    const __half* pfbase = g_wih2 + (size_t)(j0 + warp) * Hh;
    uint4 pf0 = {0,0,0,0}, pf1 = {0,0,0,0}, pf2 = {0,0,0,0}, pf3 = {0,0,0,0};

    gbar_arrive(++bgen);
    if (warp < nj) {
        pf0 = ((const uint4*)pfbase)[lane];
        pf1 = ((const uint4*)(pfbase + WSTRIDE))[lane];
        pf2 = ((const uint4*)(pfbase + 2 * WSTRIDE))[lane];
        pf3 = ((const uint4*)(pfbase + 3 * WSTRIDE))[lane];
    }
    gbar_wait(bgen);

    for (int t = 0; t < Tt; t++) {
        const int p = t & 1;
        const bool last = (t == Tt - 1);

        if (!last && tid < 64) {
            int q = tid >> 4, jj = tid & 15;
            if (jj < nj)
                spre[jj * 4 + q] = __half2float(
                    __ldcs(&g_pre1[(size_t)(t + 1) * G4H + q * Hh + j0 + jj]));
        }
        for (int i = tid; i < Hh / 4; i += NTHR)
            ((float4*)sA)[i] = ((const float4*)g_h1[p])[i];
        for (int i = tid; i < Hh / 4; i += NTHR)
            ((float4*)sB)[i] = ((const float4*)g_h2[p])[i];
        __syncthreads();

        const int ntask = last ? 2 * nj : 3 * nj;
        for (int task = warp; task < ntask; task += NWARP) {
            if (task < nj) {
                // W_ih2 round-0 (task == warp): k=0 from prefetch regs
                float4 r = dot4g_pf(g_wih2 + (size_t)(j0 + task) * Hh,
                                    (const ulonglong2*)sA, lane, pf0, pf1, pf2, pf3);
                if (lane == 0) {
                    float* dst = &sg2[0][task * 4];
                    dst[0] = r.x; dst[1] = r.y; dst[2] = r.z; dst[3] = r.w;
                }
            } else if (task < nj + 2) {
                // W_hh2 units 0,1: fully smem-pinned
                int j = task - nj;
                const __half* s0 = swei + (size_t)(3 * nj + j * 4) * Hh;
                float4 r = dot_pin(s0, s0 + Hh, s0 + 2 * Hh, s0 + 3 * Hh,
                                   (const ulonglong2*)sB, lane);
                if (lane == 0) {
                    float* dst = &sg2[1][j * 4];
                    dst[0] = r.x; dst[1] = r.y; dst[2] = r.z; dst[3] = r.w;
                }
            } else if (task < 2 * nj) {
                int j = task - nj;
                float4 r = dot4g(g_whh2 + (size_t)(j0 + j) * Hh,
                                 (const ulonglong2*)sB, lane);
                if (lane == 0) {
                    float* dst = &sg2[1][j * 4];
                    dst[0] = r.x; dst[1] = r.y; dst[2] = r.z; dst[3] = r.w;
                }
            } else {
                int j = task - 2 * nj;
                float4 r = dot_pin(swei + (size_t)j * Hh,
                                   swei + (size_t)(nj + j) * Hh,
                                   swei + (size_t)(2 * nj + j) * Hh,
                                   g_whh1 + ((size_t)3 * Hh + j0 + j) * Hh,
                                   (const ulonglong2*)sA, lane);
                if (lane == 0) {
                    sg1[j * 4 + 0] = r.x; sg1[j * 4 + 1] = r.y;
                    sg1[j * 4 + 2] = r.z; sg1[j * 4 + 3] = r.w;
                }
            }
        }
        __syncthreads();

        if (tid < nj) {
            float gi = sigf (sg2[0][tid*4+0] + sg2[1][tid*4+0] + sbias[tid*4+0]);
            float gf = sigf (sg2[0][tid*4+1] + sg2[1][tid*4+1] + sbias[tid*4+1]);
            float gg = tanhf(sg2[0][tid*4+2] + sg2[1][tid*4+2] + sbias[tid*4+2]);
            float go = sigf (sg2[0][tid*4+3] + sg2[1][tid*4+3] + sbias[tid*4+3]);
            float c = gf * sc2[tid] + gi * gg;
            sc2[tid] = c;
            float hn = go * tanhf(c);
            g_h2[1 - p][j0 + tid] = hn;
            __stcs(&g_h2hist[t][j0 + tid], hn);
        } else if (tid >= 32 && tid < 32 + nj && !last) {
            int u = tid - 32;
            float gi = sigf (sg1[u*4+0] + spre[u*4+0]);
            float gf = sigf (sg1[u*4+1] + spre[u*4+1]);
            float gg = tanhf(sg1[u*4+2] + spre[u*4+2]);
            float go = sigf (sg1[u*4+3] + spre[u*4+3]);
            float c = gf * sc1[u] + gi * gg;
            sc1[u] = c;
            g_h1[1 - p][j0 + u] = go * tanhf(c);
        }

        gbar_arrive(++bgen);
        if (warp < nj && !last) {
            pf0 = ((const uint4*)pfbase)[lane];
            pf1 = ((const uint4*)(pfbase + WSTRIDE))[lane];
            pf2 = ((const uint4*)(pfbase + 2 * WSTRIDE))[lane];
            pf3 = ((const uint4*)(pfbase + 3 * WSTRIDE))[lane];
        }
        gbar_wait(bgen);
    }
}

// ---------------- kernel 3: output projection --------------------------------
__global__ void proj_kernel(const float* __restrict__ W_lin,
                            const float* __restrict__ b_lin,
                            float* __restrict__ out,
                            int prelen) {
    __shared__ float sh[Hh];
    const int t = prelen + blockIdx.x;
    const int tid = threadIdx.x;
    const int lane = tid & 31;
    const int warp = tid >> 5;

    for (int i = tid; i < Hh / 4; i += 256)
        ((float4*)sh)[i] = ((const float4*)&g_h2hist[t][0])[i];
    __syncthreads();

    for (int d = warp; d < Dd; d += 8) {
        float s = warp_dot((const float4*)(W_lin + (size_t)d * Hh),
                           (const float4*)sh, lane);
        if (lane == 0) out[(size_t)blockIdx.x * Dd + d] = s + b_lin[d];
    }
}

extern "C" void kernel_launch(void* const* d_in, const int* in_sizes, int n_in,
                              void* d_out, int out_size) {
    const float* y     = (const float*)d_in[0];
    const float* W_ih1 = (const float*)d_in[1];
    const float* W_hh1 = (const float*)d_in[2];
    const float* b_ih1 = (const float*)d_in[3];
    const float* b_hh1 = (const float*)d_in[4];
    const float* W_ih2 = (const float*)d_in[5];
    const float* W_hh2 = (const float*)d_in[6];
    const float* b_ih2 = (const float*)d_in[7];
    const float* b_hh2 = (const float*)d_in[8];
    const float* W_lin = (const float*)d_in[9];
    const float* b_lin = (const float*)d_in[10];
    (void)in_sizes; (void)n_in;

    const int nt = out_size / Dd;
    const int prelen = Tt - nt;

    cudaFuncSetAttribute(lstm_kernel,
                         cudaFuncAttributeMaxDynamicSharedMemorySize,
                         (int)SWBYTES);

    cvt_kernel<<<2048, 256>>>(W_hh1, W_ih2, W_hh2);
    dim3 g1(G4H / 128, Tt / 64);
    pre1_kernel<<<g1, 128>>>(y, W_ih1, b_ih1, b_hh1);
    lstm_kernel<<<NBLK, NTHR, SWBYTES>>>(b_ih2, b_hh2);
    proj_kernel<<<nt, 256>>>(W_lin, b_lin, (float*)d_out, prelen);
}

// round 13
// speedup vs baseline: 2.6236x; 1.1547x over previous
#include <cuda_runtime.h>
#include <cuda_fp16.h>
#include <math.h>

#define Hh 2048
#define Tt 4096
#define Dd 66
#define G4H (4*Hh)
#define NBLK 148
#define NTHR 512
#define NWARP (NTHR/32)
#define NJMAX 14
#define WELEM ((size_t)G4H*(size_t)Hh)
#define WSTRIDE ((size_t)Hh*(size_t)Hh)
// pinned: 3*nj rows W_hh1 (i,f,g) + 8 rows W_hh2 (units 0,1 all gates)
#define SWBYTES ((3*NJMAX + 8)*Hh*sizeof(__half))   // 204800 B
#define PACKED_ONE 0x3F8000003F800000ull

// ---------------- persistent device state (static; no runtime allocs) -------
__device__ float  g_h1[2][Hh];
__device__ float  g_h2[2][Hh];
__device__ float  g_h2hist[Tt][Hh];                // 33.5 MB
__device__ __half g_pre1[(size_t)Tt * G4H];        // 67 MB fp16 (streamed, .cs)
__device__ __half g_whh1[WELEM];                   // 33.5 MB fp16
__device__ __half g_wih2[WELEM];
__device__ __half g_whh2[WELEM];

// flag barrier state (monotonic across graph replays) — central-release
__device__ volatile unsigned g_arrive[NBLK];
__device__ volatile unsigned g_release;

__device__ __forceinline__ float sigf(float x) { return 1.0f / (1.0f + expf(-x)); }

// ---------------- split central-release grid barrier --------------------------
__device__ __forceinline__ void gbar_arrive(unsigned target) {
    __syncthreads();
    if (blockIdx.x != 0 && threadIdx.x == 0) {
        __threadfence();
        g_arrive[blockIdx.x] = target;
    }
}
__device__ __forceinline__ void gbar_wait(unsigned target) {
    if (blockIdx.x == 0) {
        if (threadIdx.x > 0 && threadIdx.x < NBLK) {
            while ((int)(g_arrive[threadIdx.x] - target) < 0) { }
        }
        __syncthreads();
        if (threadIdx.x == 0) { __threadfence(); g_release = target; }
    } else {
        if (threadIdx.x == 0) {
            while ((int)(g_release - target) < 0) { }
            __threadfence();
        }
    }
    __syncthreads();
}

// ---------------- helpers ----------------------------------------------------
__device__ __forceinline__ float wreduce(float s) {
#pragma unroll
    for (int o = 16; o; o >>= 1) s += __shfl_down_sync(0xffffffffu, s, o);
    return s;
}

__device__ __forceinline__ unsigned long long cvt_h2_f2(unsigned h2) {
    unsigned long long r;
    asm("{\n\t"
        ".reg .f16 h0, h1;\n\t"
        ".reg .f32 f0, f1;\n\t"
        "mov.b32 {h0, h1}, %1;\n\t"
        "cvt.f32.f16 f0, h0;\n\t"
        "cvt.f32.f16 f1, h1;\n\t"
        "mov.b64 %0, {f0, f1};\n\t"
        "}" : "=l"(r) : "r"(h2));
    return r;
}

__device__ __forceinline__ void fma2(unsigned long long& acc,
                                     unsigned long long a,
                                     unsigned long long b) {
    asm("fma.rn.f32x2 %0, %1, %2, %3;" : "=l"(acc) : "l"(a), "l"(b), "l"(acc));
}

__device__ __forceinline__ float accsum(unsigned long long a) {
    float lo, hi;
    asm("mov.b64 {%0, %1}, %2;" : "=f"(lo), "=f"(hi) : "l"(a));
    return lo + hi;
}

// fp16 chunk inner product: 8 weights x 8 h (both fp16, uint4-packed).
// 1 HMUL2 + 3 HFMA2 in fp16 (chunk of 4 adds per half-lane), then one
// conversion of the chunk sum into the fp32x2 accumulator. CVTs: 2 (was 8).
__device__ __forceinline__ void duh(uint4 w, uint4 h, unsigned long long& accf) {
    __half2 a =         __hmul2(*(__half2*)&w.x, *(__half2*)&h.x);
    a = __hfma2(*(__half2*)&w.y, *(__half2*)&h.y, a);
    a = __hfma2(*(__half2*)&w.z, *(__half2*)&h.z, a);
    a = __hfma2(*(__half2*)&w.w, *(__half2*)&h.w, a);
    fma2(accf, cvt_h2_f2(*(unsigned*)&a), PACKED_ONE);
}

// 4 gate rows streaming; h fp16 in smem (hv, uint4-indexed like weights)
__device__ __forceinline__ float4 dot4g(const __half* __restrict__ w0,
                                        const uint4* __restrict__ hv, int lane) {
    const uint4* p0 = (const uint4*)w0;
    const uint4* p1 = (const uint4*)(w0 + WSTRIDE);
    const uint4* p2 = (const uint4*)(w0 + 2 * WSTRIDE);
    const uint4* p3 = (const uint4*)(w0 + 3 * WSTRIDE);
    unsigned long long a0 = 0ull, a1 = 0ull, a2 = 0ull, a3 = 0ull;
#pragma unroll 2
    for (int k = 0; k < 8; k++) {
        int idx = k * 32 + lane;
        uint4 h = hv[idx];
        duh(p0[idx], h, a0);
        duh(p1[idx], h, a1);
        duh(p2[idx], h, a2);
        duh(p3[idx], h, a3);
    }
    return make_float4(wreduce(accsum(a0)), wreduce(accsum(a1)),
                       wreduce(accsum(a2)), wreduce(accsum(a3)));
}

// streaming with k=0 prefetched across the barrier window
__device__ __forceinline__ float4 dot4g_pf(const __half* __restrict__ w0,
                                           const uint4* __restrict__ hv, int lane,
                                           uint4 f0, uint4 f1, uint4 f2, uint4 f3) {
    const uint4* p0 = (const uint4*)w0;
    const uint4* p1 = (const uint4*)(w0 + WSTRIDE);
    const uint4* p2 = (const uint4*)(w0 + 2 * WSTRIDE);
    const uint4* p3 = (const uint4*)(w0 + 3 * WSTRIDE);
    unsigned long long a0 = 0ull, a1 = 0ull, a2 = 0ull, a3 = 0ull;
    {
        uint4 h = hv[lane];
        duh(f0, h, a0);
        duh(f1, h, a1);
        duh(f2, h, a2);
        duh(f3, h, a3);
    }
#pragma unroll 2
    for (int k = 1; k < 8; k++) {
        int idx = k * 32 + lane;
        uint4 h = hv[idx];
        duh(p0[idx], h, a0);
        duh(p1[idx], h, a1);
        duh(p2[idx], h, a2);
        duh(p3[idx], h, a3);
    }
    return make_float4(wreduce(accsum(a0)), wreduce(accsum(a1)),
                       wreduce(accsum(a2)), wreduce(accsum(a3)));
}

// 4 gate rows from explicit pointers (smem and/or global)
__device__ __forceinline__ float4 dot_pin(const __half* si, const __half* sf,
                                          const __half* sg,
                                          const __half* wo,
                                          const uint4* __restrict__ hv, int lane) {
    const uint4* pi = (const uint4*)si;
    const uint4* pf = (const uint4*)sf;
    const uint4* pg = (const uint4*)sg;
    const uint4* po = (const uint4*)wo;
    unsigned long long a0 = 0ull, a1 = 0ull, a2 = 0ull, a3 = 0ull;
#pragma unroll 2
    for (int k = 0; k < 8; k++) {
        int idx = k * 32 + lane;
        uint4 h = hv[idx];
        duh(pi[idx], h, a0);
        duh(pf[idx], h, a1);
        duh(pg[idx], h, a2);
        duh(po[idx], h, a3);
    }
    return make_float4(wreduce(accsum(a0)), wreduce(accsum(a1)),
                       wreduce(accsum(a2)), wreduce(accsum(a3)));
}

// fp32 warp dot (proj kernel only)
__device__ __forceinline__ float warp_dot(const float4* __restrict__ w,
                                          const float4* __restrict__ sh,
                                          int lane) {
    float ax = 0.f, ay = 0.f, az = 0.f, aw = 0.f;
#pragma unroll
    for (int k = 0; k < 16; k++) {
        float4 wv = w[k * 32 + lane];
        float4 hv = sh[k * 32 + lane];
        ax += wv.x * hv.x; ay += wv.y * hv.y;
        az += wv.z * hv.z; aw += wv.w * hv.w;
    }
    return wreduce((ax + ay) + (az + aw));
}

// ---------------- kernel 0: fp32 -> fp16 weight conversion -------------------
__global__ void cvt_kernel(const float* __restrict__ A,
                           const float* __restrict__ B,
                           const float* __restrict__ C) {
    size_t n4 = WELEM / 4;
    size_t stride = (size_t)gridDim.x * blockDim.x;
    for (size_t i = (size_t)blockIdx.x * blockDim.x + threadIdx.x; i < n4; i += stride) {
        float4 a = ((const float4*)A)[i];
        float4 b = ((const float4*)B)[i];
        float4 c = ((const float4*)C)[i];
        ((__half2*)g_whh1)[2*i]   = __floats2half2_rn(a.x, a.y);
        ((__half2*)g_whh1)[2*i+1] = __floats2half2_rn(a.z, a.w);
        ((__half2*)g_wih2)[2*i]   = __floats2half2_rn(b.x, b.y);
        ((__half2*)g_wih2)[2*i+1] = __floats2half2_rn(b.z, b.w);
        ((__half2*)g_whh2)[2*i]   = __floats2half2_rn(c.x, c.y);
        ((__half2*)g_whh2)[2*i+1] = __floats2half2_rn(c.z, c.w);
    }
}

// ---------------- kernel 1: pre1[t][row] = b1 + W_ih1[row,:] @ y[t,:] --------
__global__ void pre1_kernel(const float* __restrict__ y,
                            const float* __restrict__ W_ih1,
                            const float* __restrict__ b_ih1,
                            const float* __restrict__ b_hh1) {
    __shared__ float sy[64 * Dd];
    int row = blockIdx.x * 128 + threadIdx.x;
    int t0 = blockIdx.y * 64;
    for (int i = threadIdx.x; i < 64 * Dd; i += 128)
        sy[i] = y[(size_t)t0 * Dd + i];
    __syncthreads();

    float w[Dd];
#pragma unroll
    for (int k = 0; k < Dd; k++) w[k] = W_ih1[(size_t)row * Dd + k];
    float b = b_ih1[row] + b_hh1[row];

    for (int tt = 0; tt < 64; tt++) {
        float acc = b;
#pragma unroll
        for (int k = 0; k < Dd; k++) acc += w[k] * sy[tt * Dd + k];
        __stcs(&g_pre1[(size_t)(t0 + tt) * G4H + row], __float2half_rn(acc));
    }
}

// ---------------- kernel 2: persistent fused LSTM (1 barrier / step) ---------
// fp16 HFMA2 dot engine (chunked fp16 accumulate, fp32x2 chunk fold).
// h staged in smem as fp16. Pinned smem: W_hh1 i/f/g + W_hh2 units 0,1.
__global__ void __launch_bounds__(NTHR, 1)
lstm_kernel(const float* __restrict__ b_ih2,
            const float* __restrict__ b_hh2) {
    extern __shared__ __half swei[];   // [3*nj + 8][Hh]
    __shared__ __half sAh[Hh];      // h1[t] fp16
    __shared__ __half sBh[Hh];      // h2[t-1] fp16
    __shared__ float sg1[64];
    __shared__ float sg2[2][64];
    __shared__ float sbias[64];
    __shared__ float spre[64];
    __shared__ float sc1[16];
    __shared__ float sc2[16];

    const int tid  = threadIdx.x;
    const int lane = tid & 31;
    const int warp = tid >> 5;
    const int b    = blockIdx.x;

    const int base  = Hh / NBLK;          // 13
    const int extra = Hh % NBLK;          // 124
    const int nj = base + (b < extra ? 1 : 0);
    const int j0 = b * base + (b < extra ? b : extra);

    unsigned bgen = g_release;

    // pin W_hh1 i,f,g rows + W_hh2 units 0,1 into smem (coalesced, one-time)
    const int segs = Hh / 8;               // 256 uint4 per row
    const int prows = 3 * nj + 8;
    for (int i = tid; i < prows * segs; i += NTHR) {
        int row = i / segs;
        int seg = i - row * segs;
        const __half* src;
        if (row < 3 * nj) {
            int g = row / nj, j = row - g * nj;
            src = g_whh1 + ((size_t)g * Hh + j0 + j) * Hh;
        } else {
            int rr = row - 3 * nj;
            int j = rr >> 2, q = rr & 3;
            src = g_whh2 + ((size_t)q * Hh + j0 + j) * Hh;
        }
        ((uint4*)(swei + (size_t)row * Hh))[seg] = ((const uint4*)src)[seg];
    }

    for (int j = tid; j < nj; j += NTHR) g_h2[0][j0 + j] = 0.f;
    for (int r = tid; r < 4 * nj; r += NTHR) {
        int j = r >> 2, q = r & 3;
        sbias[r] = b_ih2[q * Hh + j0 + j] + b_hh2[q * Hh + j0 + j];
    }
    if (tid < 16) { sc1[tid] = 0.f; sc2[tid] = 0.f; }
    __syncthreads();

    // prologue: h1[0] = cell1(x0, 0, 0)
    if (tid < nj) {
        size_t pb = (size_t)j0 + tid;
        float gi = sigf (__half2float(__ldcs(&g_pre1[pb])));
        float gg = tanhf(__half2float(__ldcs(&g_pre1[pb + 2 * Hh])));
        float go = sigf (__half2float(__ldcs(&g_pre1[pb + 3 * Hh])));
        float c = gi * gg;
        sc1[tid] = c;
        g_h1[0][j0 + tid] = go * tanhf(c);
    }

    const __half* pfbase = g_wih2 + (size_t)(j0 + warp) * Hh;
    uint4 pf0 = {0,0,0,0}, pf1 = {0,0,0,0}, pf2 = {0,0,0,0}, pf3 = {0,0,0,0};

    gbar_arrive(++bgen);
    if (warp < nj) {
        pf0 = ((const uint4*)pfbase)[lane];
        pf1 = ((const uint4*)(pfbase + WSTRIDE))[lane];
        pf2 = ((const uint4*)(pfbase + 2 * WSTRIDE))[lane];
        pf3 = ((const uint4*)(pfbase + 3 * WSTRIDE))[lane];
    }
    gbar_wait(bgen);

    for (int t = 0; t < Tt; t++) {
        const int p = t & 1;
        const bool last = (t == Tt - 1);

        if (!last && tid < 64) {
            int q = tid >> 4, jj = tid & 15;
            if (jj < nj)
                spre[jj * 4 + q] = __half2float(
                    __ldcs(&g_pre1[(size_t)(t + 1) * G4H + q * Hh + j0 + jj]));
        }
        // stage h1[t], h2[t-1] as fp16
        for (int i = tid; i < Hh / 4; i += NTHR) {
            float4 v = ((const float4*)g_h1[p])[i];
            ((__half2*)sAh)[2*i]   = __floats2half2_rn(v.x, v.y);
            ((__half2*)sAh)[2*i+1] = __floats2half2_rn(v.z, v.w);
            float4 w = ((const float4*)g_h2[p])[i];
            ((__half2*)sBh)[2*i]   = __floats2half2_rn(w.x, w.y);
            ((__half2*)sBh)[2*i+1] = __floats2half2_rn(w.z, w.w);
        }
        __syncthreads();

        const int ntask = last ? 2 * nj : 3 * nj;
        for (int task = warp; task < ntask; task += NWARP) {
            if (task < nj) {
                // W_ih2 round-0 (task == warp): k=0 from prefetch regs
                float4 r = dot4g_pf(g_wih2 + (size_t)(j0 + task) * Hh,
                                    (const uint4*)sAh, lane, pf0, pf1, pf2, pf3);
                if (lane == 0) {
                    float* dst = &sg2[0][task * 4];
                    dst[0] = r.x; dst[1] = r.y; dst[2] = r.z; dst[3] = r.w;
                }
            } else if (task < nj + 2) {
                // W_hh2 units 0,1: fully smem-pinned
                int j = task - nj;
                const __half* s0 = swei + (size_t)(3 * nj + j * 4) * Hh;
                float4 r = dot_pin(s0, s0 + Hh, s0 + 2 * Hh, s0 + 3 * Hh,
                                   (const uint4*)sBh, lane);
                if (lane == 0) {
                    float* dst = &sg2[1][j * 4];
                    dst[0] = r.x; dst[1] = r.y; dst[2] = r.z; dst[3] = r.w;
                }
            } else if (task < 2 * nj) {
                int j = task - nj;
                float4 r = dot4g(g_whh2 + (size_t)(j0 + j) * Hh,
                                 (const uint4*)sBh, lane);
                if (lane == 0) {
                    float* dst = &sg2[1][j * 4];
                    dst[0] = r.x; dst[1] = r.y; dst[2] = r.z; dst[3] = r.w;
                }
            } else {
                int j = task - 2 * nj;
                float4 r = dot_pin(swei + (size_t)j * Hh,
                                   swei + (size_t)(nj + j) * Hh,
                                   swei + (size_t)(2 * nj + j) * Hh,
                                   g_whh1 + ((size_t)3 * Hh + j0 + j) * Hh,
                                   (const uint4*)sAh, lane);
                if (lane == 0) {
                    sg1[j * 4 + 0] = r.x; sg1[j * 4 + 1] = r.y;
                    sg1[j * 4 + 2] = r.z; sg1[j * 4 + 3] = r.w;
                }
            }
        }
        __syncthreads();

        if (tid < nj) {
            float gi = sigf (sg2[0][tid*4+0] + sg2[1][tid*4+0] + sbias[tid*4+0]);
            float gf = sigf (sg2[0][tid*4+1] + sg2[1][tid*4+1] + sbias[tid*4+1]);
            float gg = tanhf(sg2[0][tid*4+2] + sg2[1][tid*4+2] + sbias[tid*4+2]);
            float go = sigf (sg2[0][tid*4+3] + sg2[1][tid*4+3] + sbias[tid*4+3]);
            float c = gf * sc2[tid] + gi * gg;
            sc2[tid] = c;
            float hn = go * tanhf(c);
            g_h2[1 - p][j0 + tid] = hn;
            __stcs(&g_h2hist[t][j0 + tid], hn);
        } else if (tid >= 32 && tid < 32 + nj && !last) {
            int u = tid - 32;
            float gi = sigf (sg1[u*4+0] + spre[u*4+0]);
            float gf = sigf (sg1[u*4+1] + spre[u*4+1]);
            float gg = tanhf(sg1[u*4+2] + spre[u*4+2]);
            float go = sigf (sg1[u*4+3] + spre[u*4+3]);
            float c = gf * sc1[u] + gi * gg;
            sc1[u] = c;
            g_h1[1 - p][j0 + u] = go * tanhf(c);
        }

        gbar_arrive(++bgen);
        if (warp < nj && !last) {
            pf0 = ((const uint4*)pfbase)[lane];
            pf1 = ((const uint4*)(pfbase + WSTRIDE))[lane];
            pf2 = ((const uint4*)(pfbase + 2 * WSTRIDE))[lane];
            pf3 = ((const uint4*)(pfbase + 3 * WSTRIDE))[lane];
        }
        gbar_wait(bgen);
    }
}

// ---------------- kernel 3: output projection --------------------------------
__global__ void proj_kernel(const float* __restrict__ W_lin,
                            const float* __restrict__ b_lin,
                            float* __restrict__ out,
                            int prelen) {
    __shared__ float sh[Hh];
    const int t = prelen + blockIdx.x;
    const int tid = threadIdx.x;
    const int lane = tid & 31;
    const int warp = tid >> 5;

    for (int i = tid; i < Hh / 4; i += 256)
        ((float4*)sh)[i] = ((const float4*)&g_h2hist[t][0])[i];
    __syncthreads();

    for (int d = warp; d < Dd; d += 8) {
        float s = warp_dot((const float4*)(W_lin + (size_t)d * Hh),
                           (const float4*)sh, lane);
        if (lane == 0) out[(size_t)blockIdx.x * Dd + d] = s + b_lin[d];
    }
}

extern "C" void kernel_launch(void* const* d_in, const int* in_sizes, int n_in,
                              void* d_out, int out_size) {
    const float* y     = (const float*)d_in[0];
    const float* W_ih1 = (const float*)d_in[1];
    const float* W_hh1 = (const float*)d_in[2];
    const float* b_ih1 = (const float*)d_in[3];
    const float* b_hh1 = (const float*)d_in[4];
    const float* W_ih2 = (const float*)d_in[5];
    const float* W_hh2 = (const float*)d_in[6];
    const float* b_ih2 = (const float*)d_in[7];
    const float* b_hh2 = (const float*)d_in[8];
    const float* W_lin = (const float*)d_in[9];
    const float* b_lin = (const float*)d_in[10];
    (void)in_sizes; (void)n_in;

    const int nt = out_size / Dd;
    const int prelen = Tt - nt;

    cudaFuncSetAttribute(lstm_kernel,
                         cudaFuncAttributeMaxDynamicSharedMemorySize,
                         (int)SWBYTES);

    cvt_kernel<<<2048, 256>>>(W_hh1, W_ih2, W_hh2);
    dim3 g1(G4H / 128, Tt / 64);
    pre1_kernel<<<g1, 128>>>(y, W_ih1, b_ih1, b_hh1);
    lstm_kernel<<<NBLK, NTHR, SWBYTES>>>(b_ih2, b_hh2);
    proj_kernel<<<nt, 256>>>(W_lin, b_lin, (float*)d_out, prelen);
}